// round 11
// baseline (speedup 1.0000x reference)
#include <cuda_runtime.h>
#include <cuda_bf16.h>
#include <cstdint>
#include <cstddef>

#define BATCH 1024
#define NA 48
#define NB 24
#define DIM 680
#define DIMP 768                 // padded feature count
#define GTOT (NA*NB*NA)          // 55296
#define NDIM2 (DIM*DIM)

// ---- gram config ----
#define SPLITK 36
#define KPS (GTOT/SPLITK)        // 1536
#define GBK 32
#define TOTIT (KPS/GBK)          // 48
#define NSTG 4
#define GBM 128
#define GBN 128
#define GPITCH 40                // bf16 pitch: 32 + 8 pad (80B rows, conflict-free)
#define ASTG (GBM*GPITCH*2)      // 10240 B
#define STAGEB (2*ASTG)          // 20480 B
#define NTILES 57                // 21 C1 (j>=i) + 36 C2
#define TILE_ELEMS (GBM*GBN)     // 16384

// ---- out_kernel config ----
#define OBM 64                   // F rows per CTA
#define OBN 128                  // i cols per CTA
#define BK 32
#define FPITCH 40
#define MPITCH 136

// ---- scratch (no allocations allowed) ----
__device__ __nv_bfloat16 gZh[(size_t)DIMP * GTOT];   // ~85MB
__device__ __nv_bfloat16 gZl[(size_t)DIMP * GTOT];   // ~85MB
__device__ float gP[(size_t)NTILES * SPLITK * TILE_ELEMS];  // ~134.5MB
__device__ float gS1[NDIM2];
__device__ float gS2[NDIM2];
__device__ float gM[NDIM2];

// tile tables: C1 (pass0, Zh*Zh) on j>=i triangle; C2 (pass1, Zh*Zl) on all 36
__constant__ int cMI[NTILES] = {
    0,0,0,0,0,0, 1,1,1,1,1, 2,2,2,2, 3,3,3, 4,4, 5,
    0,0,0,0,0,0, 1,1,1,1,1,1, 2,2,2,2,2,2, 3,3,3,3,3,3, 4,4,4,4,4,4, 5,5,5,5,5,5};
__constant__ int cNJ[NTILES] = {
    0,1,2,3,4,5, 1,2,3,4,5, 2,3,4,5, 3,4,5, 4,5, 5,
    0,1,2,3,4,5, 0,1,2,3,4,5, 0,1,2,3,4,5, 0,1,2,3,4,5, 0,1,2,3,4,5, 0,1,2,3,4,5};
__constant__ int cPASS[NTILES] = {
    0,0,0,0,0,0,0,0,0,0,0,0,0,0,0,0,0,0,0,0,0,
    1,1,1,1,1,1,1,1,1,1,1,1,1,1,1,1,1,1,
    1,1,1,1,1,1,1,1,1,1,1,1,1,1,1,1,1,1};

// ---------------------------------------------------------------- helpers
__device__ __forceinline__ uint32_t smem_u32(const void* p) {
    return (uint32_t)__cvta_generic_to_shared(p);
}
__device__ __forceinline__ void split_bf16(float z, __nv_bfloat16& h, __nv_bfloat16& l) {
    h = __float2bfloat16(z);
    l = __float2bfloat16(z - __bfloat162float(h));
}
__device__ __forceinline__ uint32_t pack2h(__nv_bfloat16 a, __nv_bfloat16 b) {
    uint16_t ua = *reinterpret_cast<uint16_t*>(&a);
    uint16_t ub = *reinterpret_cast<uint16_t*>(&b);
    return (uint32_t)ua | ((uint32_t)ub << 16);
}
__device__ __forceinline__ void cp_async16(uint32_t dst, const void* src) {
    asm volatile("cp.async.cg.shared.global [%0], [%1], 16;\n" :: "r"(dst), "l"(src));
}
__device__ __forceinline__ void cp_commit() {
    asm volatile("cp.async.commit_group;\n" ::: "memory");
}
__device__ __forceinline__ void ldsm4(uint32_t (&r)[4], uint32_t addr) {
    asm volatile("ldmatrix.sync.aligned.m8n8.x4.shared.b16 {%0,%1,%2,%3}, [%4];"
                 : "=r"(r[0]), "=r"(r[1]), "=r"(r[2]), "=r"(r[3]) : "r"(addr));
}
__device__ __forceinline__ void ldsm4t(uint32_t (&r)[4], uint32_t addr) {
    asm volatile("ldmatrix.sync.aligned.m8n8.x4.trans.shared.b16 {%0,%1,%2,%3}, [%4];"
                 : "=r"(r[0]), "=r"(r[1]), "=r"(r[2]), "=r"(r[3]) : "r"(addr));
}
__device__ __forceinline__ void mma_bf16(float (&d)[4], const uint32_t (&a)[4],
                                         uint32_t b0, uint32_t b1) {
    asm volatile(
        "mma.sync.aligned.m16n8k16.row.col.f32.bf16.bf16.f32 "
        "{%0,%1,%2,%3}, {%4,%5,%6,%7}, {%8,%9}, {%0,%1,%2,%3};\n"
        : "+f"(d[0]), "+f"(d[1]), "+f"(d[2]), "+f"(d[3])
        : "r"(a[0]), "r"(a[1]), "r"(a[2]), "r"(a[3]), "r"(b0), "r"(b1));
}

// ---------------------------------------------------------------- kernel 1
// transpose + weight + bf16 split: gZh/gZl[i][g] = split( sqrt(qw_g) * D[g][i] )
#define TPP 65
extern "C" __global__ void __launch_bounds__(256)
transpose_kernel(const float* __restrict__ D, const float* __restrict__ qw) {
    __shared__ float s[64][TPP];
    __shared__ float sqw[NB];
    const int tid = threadIdx.x;
    if (tid < NB) sqw[tid] = sqrtf(qw[tid]);
    __syncthreads();
    const int gbase = blockIdx.x * 64;
    const int ibase = blockIdx.y * 64;

#pragma unroll
    for (int p = 0; p < 4; p++) {
        int g_l = (tid >> 4) + 16 * p;
        int i_l = (tid & 15) * 4;
        int g = gbase + g_l;
        float w = sqw[(g / NA) % NB];
        float4 v = (ibase + i_l < DIM)
                 ? *(const float4*)(D + (size_t)g * DIM + ibase + i_l)
                 : make_float4(0.f, 0.f, 0.f, 0.f);
        s[g_l][i_l]     = v.x * w;
        s[g_l][i_l + 1] = v.y * w;
        s[g_l][i_l + 2] = v.z * w;
        s[g_l][i_l + 3] = v.w * w;
    }
    __syncthreads();

    const int i_l = tid >> 2;
    const int gc  = (tid & 3) * 16;
    uint32_t hi[8], lo[8];
#pragma unroll
    for (int q = 0; q < 8; q++) {
        float a = s[gc + 2 * q][i_l];
        float b = s[gc + 2 * q + 1][i_l];
        __nv_bfloat16 ha, la, hb, lb;
        split_bf16(a, ha, la);
        split_bf16(b, hb, lb);
        hi[q] = pack2h(ha, hb);
        lo[q] = pack2h(la, lb);
    }
    size_t ro = (size_t)(ibase + i_l) * GTOT + gbase + gc;
    *(uint4*)(gZh + ro)     = make_uint4(hi[0], hi[1], hi[2], hi[3]);
    *(uint4*)(gZh + ro + 8) = make_uint4(hi[4], hi[5], hi[6], hi[7]);
    *(uint4*)(gZl + ro)     = make_uint4(lo[0], lo[1], lo[2], lo[3]);
    *(uint4*)(gZl + ro + 8) = make_uint4(lo[4], lo[5], lo[6], lo[7]);
}

// ---------------------------------------------------------------- kernel 2
// gram: tile e, split z -> gP[e][z] = A(128 rows Zh) @ B(128 rows Zh|Zl)^T
// 256 threads, 2 CTAs/SM; SPLITK=36 -> 2052 CTAs = 6.93 waves (1% quantization)
extern "C" __global__ void __launch_bounds__(256, 2)
gram_mm() {
    extern __shared__ char dsm[];
    const uint32_t sbase = smem_u32(dsm);

    const int e     = blockIdx.x;
    const int split = blockIdx.y;
    const int ibase = cMI[e] * GBM;
    const int jbase = cNJ[e] * GBN;
    const size_t g0 = (size_t)split * KPS;
    const __nv_bfloat16* Brows = cPASS[e] ? gZl : gZh;

    const int tid  = threadIdx.x;
    const int lane = tid & 31, warp = tid >> 5;
    const int wmB  = (warp & 1) * 64;
    const int wnB  = (warp >> 1) * 32;
    const int group = lane >> 2, tig = lane & 3;
    const int frow = lane & 15;
    const int fcol = (lane & 16) ? 8 : 0;

    float acc[4][4][4];
#pragma unroll
    for (int mi = 0; mi < 4; mi++)
#pragma unroll
        for (int nb = 0; nb < 4; nb++)
#pragma unroll
            for (int r = 0; r < 4; r++) acc[mi][nb][r] = 0.f;

    // fill: A 512 + B 512 16B chunks, 4 per thread
    auto fill = [&](int it) {
        const uint32_t stg = sbase + (uint32_t)(it & (NSTG - 1)) * STAGEB;
        const size_t gofs = g0 + (size_t)it * GBK;
#pragma unroll
        for (int p = 0; p < 2; p++) {
            int c = tid + 256 * p;
            int row = c >> 2, col16 = c & 3;
            cp_async16(stg + row * 80 + col16 * 16,
                       gZh + (size_t)(ibase + row) * GTOT + gofs + col16 * 8);
            cp_async16(stg + ASTG + row * 80 + col16 * 16,
                       Brows + (size_t)(jbase + row) * GTOT + gofs + col16 * 8);
        }
        cp_commit();
    };

#pragma unroll
    for (int s = 0; s < NSTG - 1; s++) fill(s);   // prologue: 3 groups

    for (int it = 0; it < TOTIT; ++it) {
        if (it <= TOTIT - 3)
            asm volatile("cp.async.wait_group 2;\n" ::: "memory");
        else if (it == TOTIT - 2)
            asm volatile("cp.async.wait_group 1;\n" ::: "memory");
        else
            asm volatile("cp.async.wait_group 0;\n" ::: "memory");
        __syncthreads();

        const uint32_t stg = sbase + (uint32_t)(it & (NSTG - 1)) * STAGEB;
        const uint32_t aU = stg, bU = stg + ASTG;
#pragma unroll
        for (int kk = 0; kk < GBK; kk += 16) {
            uint32_t A4[4][4], B4[2][4];
#pragma unroll
            for (int mi = 0; mi < 4; mi++)
                ldsm4(A4[mi], aU + 2u * ((wmB + 16 * mi + frow) * GPITCH + kk + fcol));
#pragma unroll
            for (int h = 0; h < 2; h++)
                ldsm4(B4[h], bU + 2u * ((wnB + 16 * h + frow) * GPITCH + kk + fcol));
#pragma unroll
            for (int mi = 0; mi < 4; mi++)
#pragma unroll
                for (int nb = 0; nb < 4; nb++)
                    mma_bf16(acc[mi][nb], A4[mi],
                             B4[nb >> 1][nb & 1], B4[nb >> 1][(nb & 1) + 2]);
        }
        const int f = it + (NSTG - 1);
        if (f < TOTIT) fill(f);
    }

    // epilogue: per-tile partial [128][128] fp32
    float* P = gP + ((size_t)(e * SPLITK + split)) * TILE_ELEMS;
#pragma unroll
    for (int mi = 0; mi < 4; mi++) {
        int r1 = wmB + 16 * mi + group;
        int r2 = r1 + 8;
#pragma unroll
        for (int nb = 0; nb < 4; nb++) {
            int c0 = wnB + 8 * nb + 2 * tig;
            P[(size_t)r1 * GBN + c0]     = acc[mi][nb][0];
            P[(size_t)r1 * GBN + c0 + 1] = acc[mi][nb][1];
            P[(size_t)r2 * GBN + c0]     = acc[mi][nb][2];
            P[(size_t)r2 * GBN + c0 + 1] = acc[mi][nb][3];
        }
    }
}

// ---------------------------------------------------------------- kernel 3
extern "C" __global__ void reduce_tc() {
    size_t idx = (size_t)blockIdx.x * 256 + threadIdx.x;
    if (idx >= (size_t)NTILES * TILE_ELEMS) return;
    const int e  = (int)(idx >> 14);
    const int rc = (int)(idx & 16383);
    float sum = 0.f;
#pragma unroll 9
    for (int p = 0; p < SPLITK; p++)
        sum += gP[(((size_t)(e * SPLITK + p)) << 14) + rc];
    const int r = rc >> 7, c = rc & 127;
    const int i = cMI[e] * GBM + r;
    const int j = cNJ[e] * GBN + c;
    if (i < DIM && j < DIM)
        (cPASS[e] ? gS2 : gS1)[(size_t)i * DIM + j] = sum;
}

// ---------------------------------------------------------------- kernel 4
// M = C1(sym) + C2 + C2^T ; C1 block (bi,bj) computed iff bj >= bi
extern "C" __global__ void sym_kernel() {
    int idx = blockIdx.x * blockDim.x + threadIdx.x;
    if (idx < NDIM2) {
        int i = idx / DIM;
        int j = idx - i * DIM;
        float c1 = ((j >> 7) >= (i >> 7)) ? gS1[idx] : gS1[(size_t)j * DIM + i];
        gM[idx] = c1 + gS2[idx] + gS2[(size_t)j * DIM + i];
    }
}

// ---------------------------------------------------------------- kernel 5
// out = F @ M  (3-term bf16 split; OBM=64 -> 96 CTAs for latency hiding)
extern "C" __global__ void __launch_bounds__(256)
out_kernel(const float* __restrict__ F, float* __restrict__ out) {
    __shared__ __nv_bfloat16 sFh[OBM * FPITCH], sFl[OBM * FPITCH];
    __shared__ __nv_bfloat16 sMh[BK * MPITCH], sMl[BK * MPITCH];

    const int tid   = threadIdx.x;
    const int nbase = blockIdx.x * OBM;
    const int ibase = blockIdx.y * OBN;

    const int lane = tid & 31, warp = tid >> 5;
    const int wm = (warp & 1) * 32;
    const int wn = (warp >> 1) * 32;
    const int group = lane >> 2, tig = lane & 3;
    const int frow = lane & 15;
    const int fcol = (lane & 16) ? 8 : 0;
    const int brow = (lane & 7) + ((lane & 8) ? 8 : 0);
    const int bcol = (lane & 16) ? 8 : 0;

    const uint32_t fhU = smem_u32(sFh), flU = smem_u32(sFl);
    const uint32_t mhU = smem_u32(sMh), mlU = smem_u32(sMl);

    float acc[2][4][4];
#pragma unroll
    for (int mi = 0; mi < 2; mi++)
#pragma unroll
        for (int nb = 0; nb < 4; nb++)
#pragma unroll
            for (int r = 0; r < 4; r++) acc[mi][nb][r] = 0.f;

    const int NIT = (DIM + BK - 1) / BK;

    for (int it = 0; it < NIT; ++it) {
        const int k0 = it * BK;
        {   // F tile: 64 rows x 32 k = 512 float4 chunks, 2 per thread
            const int c = (tid & 7) * 4;
            const bool v = (k0 + c) < DIM;
#pragma unroll
            for (int p = 0; p < 2; p++) {
                int row = (tid >> 3) + 32 * p;
                float4 f = v ? *(const float4*)(F + (size_t)(nbase + row) * DIM + k0 + c)
                             : make_float4(0.f, 0.f, 0.f, 0.f);
                __nv_bfloat16 h[4], l[4];
                split_bf16(f.x, h[0], l[0]);
                split_bf16(f.y, h[1], l[1]);
                split_bf16(f.z, h[2], l[2]);
                split_bf16(f.w, h[3], l[3]);
                int off = row * FPITCH + c;
                *(uint2*)&sFh[off] = make_uint2(pack2h(h[0], h[1]), pack2h(h[2], h[3]));
                *(uint2*)&sFl[off] = make_uint2(pack2h(l[0], l[1]), pack2h(l[2], l[3]));
            }
        }
        {   // M tile: 32 k x 128 i
            const int c = (tid & 31) * 4;
            const bool cv = (ibase + c) < DIM;
#pragma unroll
            for (int p = 0; p < 4; p++) {
                int r = (tid >> 5) + 8 * p;
                int j = k0 + r;
                bool v = cv && (j < DIM);
                float4 m = v ? *(const float4*)(gM + (size_t)j * DIM + ibase + c)
                             : make_float4(0.f, 0.f, 0.f, 0.f);
                __nv_bfloat16 h[4], l[4];
                split_bf16(m.x, h[0], l[0]);
                split_bf16(m.y, h[1], l[1]);
                split_bf16(m.z, h[2], l[2]);
                split_bf16(m.w, h[3], l[3]);
                int off = r * MPITCH + c;
                *(uint2*)&sMh[off] = make_uint2(pack2h(h[0], h[1]), pack2h(h[2], h[3]));
                *(uint2*)&sMl[off] = make_uint2(pack2h(l[0], l[1]), pack2h(l[2], l[3]));
            }
        }
        __syncthreads();

#pragma unroll
        for (int kk = 0; kk < BK; kk += 16) {
            uint32_t Ah[2][4], Al[2][4], Bh[2][4], Bl[2][4];
#pragma unroll
            for (int mi = 0; mi < 2; mi++) {
                uint32_t off = 2u * ((wm + 16 * mi + frow) * FPITCH + kk + fcol);
                ldsm4(Ah[mi], fhU + off);
                ldsm4(Al[mi], flU + off);
            }
#pragma unroll
            for (int h = 0; h < 2; h++) {
                uint32_t off = 2u * ((kk + brow) * MPITCH + wn + 16 * h + bcol);
                ldsm4t(Bh[h], mhU + off);
                ldsm4t(Bl[h], mlU + off);
            }
#pragma unroll
            for (int mi = 0; mi < 2; mi++)
#pragma unroll
                for (int nb = 0; nb < 4; nb++) {
                    const int h = nb >> 1, pr = (nb & 1) * 2;
                    mma_bf16(acc[mi][nb], Ah[mi], Bh[h][pr], Bh[h][pr + 1]);
                    mma_bf16(acc[mi][nb], Ah[mi], Bl[h][pr], Bl[h][pr + 1]);
                    mma_bf16(acc[mi][nb], Al[mi], Bh[h][pr], Bh[h][pr + 1]);
                }
        }
        __syncthreads();
    }

#pragma unroll
    for (int mi = 0; mi < 2; mi++) {
        int n1 = nbase + wm + 16 * mi + group;
        int n2 = n1 + 8;
#pragma unroll
        for (int nb = 0; nb < 4; nb++) {
            int i0 = ibase + wn + 8 * nb + 2 * tig;
            if (i0 < DIM) {
                out[(size_t)n1 * DIM + i0]     = acc[mi][nb][0];
                out[(size_t)n1 * DIM + i0 + 1] = acc[mi][nb][1];
                out[(size_t)n2 * DIM + i0]     = acc[mi][nb][2];
                out[(size_t)n2 * DIM + i0 + 1] = acc[mi][nb][3];
            }
        }
    }
}

// ---------------------------------------------------------------- launch
extern "C" void kernel_launch(void* const* d_in, const int* in_sizes, int n_in,
                              void* d_out, int out_size) {
    const float* F  = (const float*)d_in[0];   // (1024, 680)
    const float* D  = (const float*)d_in[1];   // (48, 24, 48, 680)
    const float* qw = (const float*)d_in[2];   // (24,)
    float* out = (float*)d_out;                // (1024, 680) fp32

    const int gram_smem = NSTG * STAGEB;       // 81920 B
    cudaFuncSetAttribute(gram_mm, cudaFuncAttributeMaxDynamicSharedMemorySize, gram_smem);

    transpose_kernel<<<dim3(GTOT / 64, DIMP / 64), 256>>>(D, qw);

    gram_mm<<<dim3(NTILES, SPLITK), 256, gram_smem>>>();

    reduce_tc<<<(NTILES * TILE_ELEMS + 255) / 256, 256>>>();
    sym_kernel<<<(NDIM2 + 255) / 256, 256>>>();

    dim3 ogrid(BATCH / OBM, (DIM + OBN - 1) / OBN);     // 16 x 6
    out_kernel<<<ogrid, 256>>>(F, out);
}

// round 12
// speedup vs baseline: 1.1735x; 1.1735x over previous
#include <cuda_runtime.h>
#include <cuda_bf16.h>
#include <cstdint>
#include <cstddef>

#define BATCH 1024
#define NA 48
#define NB 24
#define DIM 680
#define DIMP 768                 // padded feature count
#define GTOT (NA*NB*NA)          // 55296
#define NDIM2 (DIM*DIM)

// ---- gram config ----
#define SPLITK 8
#define KPS (GTOT/SPLITK)        // 6912
#define GBK 64
#define TOTIT (KPS/GBK)          // 108
#define NSTG 3
#define GBM 128
#define GBN 128
#define GPITCH 72                // bf16 pitch: 64 + 8 pad (144B rows, conflict-free ldsm)
#define ASTG (GBM*GPITCH*2)      // 18432 B
#define STAGEB (2*ASTG)          // 36864 B
#define NTILES 57                // 21 C1 (j>=i) + 36 C2
#define TILE_ELEMS (GBM*GBN)     // 16384

// ---- out_kernel config ----
#define OBM 64                   // F rows per CTA
#define OBN 128                  // i cols per CTA
#define BK 32
#define FPITCH 40
#define MPITCH 136

// ---- scratch (no allocations allowed) ----
__device__ __nv_bfloat16 gZh[(size_t)DIMP * GTOT];   // ~85MB
__device__ __nv_bfloat16 gZl[(size_t)DIMP * GTOT];   // ~85MB
__device__ float gP[(size_t)NTILES * SPLITK * TILE_ELEMS];  // ~29.9MB
__device__ float gS1[NDIM2];
__device__ float gS2[NDIM2];
__device__ float gM[NDIM2];

// tile tables: C1 (pass0, Zh*Zh) on j>=i triangle; C2 (pass1, Zh*Zl) on all 36
__constant__ int cMI[NTILES] = {
    0,0,0,0,0,0, 1,1,1,1,1, 2,2,2,2, 3,3,3, 4,4, 5,
    0,0,0,0,0,0, 1,1,1,1,1,1, 2,2,2,2,2,2, 3,3,3,3,3,3, 4,4,4,4,4,4, 5,5,5,5,5,5};
__constant__ int cNJ[NTILES] = {
    0,1,2,3,4,5, 1,2,3,4,5, 2,3,4,5, 3,4,5, 4,5, 5,
    0,1,2,3,4,5, 0,1,2,3,4,5, 0,1,2,3,4,5, 0,1,2,3,4,5, 0,1,2,3,4,5, 0,1,2,3,4,5};
__constant__ int cPASS[NTILES] = {
    0,0,0,0,0,0,0,0,0,0,0,0,0,0,0,0,0,0,0,0,0,
    1,1,1,1,1,1,1,1,1,1,1,1,1,1,1,1,1,1,
    1,1,1,1,1,1,1,1,1,1,1,1,1,1,1,1,1,1};

// ---------------------------------------------------------------- helpers
__device__ __forceinline__ uint32_t smem_u32(const void* p) {
    return (uint32_t)__cvta_generic_to_shared(p);
}
__device__ __forceinline__ void split_bf16(float z, __nv_bfloat16& h, __nv_bfloat16& l) {
    h = __float2bfloat16(z);
    l = __float2bfloat16(z - __bfloat162float(h));
}
__device__ __forceinline__ uint32_t pack2h(__nv_bfloat16 a, __nv_bfloat16 b) {
    uint16_t ua = *reinterpret_cast<uint16_t*>(&a);
    uint16_t ub = *reinterpret_cast<uint16_t*>(&b);
    return (uint32_t)ua | ((uint32_t)ub << 16);
}
__device__ __forceinline__ void cp_async16(uint32_t dst, const void* src) {
    asm volatile("cp.async.cg.shared.global [%0], [%1], 16;\n" :: "r"(dst), "l"(src));
}
__device__ __forceinline__ void cp_commit() {
    asm volatile("cp.async.commit_group;\n" ::: "memory");
}
__device__ __forceinline__ void ldsm4(uint32_t (&r)[4], uint32_t addr) {
    asm volatile("ldmatrix.sync.aligned.m8n8.x4.shared.b16 {%0,%1,%2,%3}, [%4];"
                 : "=r"(r[0]), "=r"(r[1]), "=r"(r[2]), "=r"(r[3]) : "r"(addr));
}
__device__ __forceinline__ void ldsm4t(uint32_t (&r)[4], uint32_t addr) {
    asm volatile("ldmatrix.sync.aligned.m8n8.x4.trans.shared.b16 {%0,%1,%2,%3}, [%4];"
                 : "=r"(r[0]), "=r"(r[1]), "=r"(r[2]), "=r"(r[3]) : "r"(addr));
}
__device__ __forceinline__ void mma_bf16(float (&d)[4], const uint32_t (&a)[4],
                                         uint32_t b0, uint32_t b1) {
    asm volatile(
        "mma.sync.aligned.m16n8k16.row.col.f32.bf16.bf16.f32 "
        "{%0,%1,%2,%3}, {%4,%5,%6,%7}, {%8,%9}, {%0,%1,%2,%3};\n"
        : "+f"(d[0]), "+f"(d[1]), "+f"(d[2]), "+f"(d[3])
        : "r"(a[0]), "r"(a[1]), "r"(a[2]), "r"(a[3]), "r"(b0), "r"(b1));
}

// ---------------------------------------------------------------- kernel 1
// transpose + weight + bf16 split: gZh/gZl[i][g] = split( sqrt(qw_g) * D[g][i] )
#define TPP 65
extern "C" __global__ void __launch_bounds__(256)
transpose_kernel(const float* __restrict__ D, const float* __restrict__ qw) {
    __shared__ float s[64][TPP];
    __shared__ float sqw[NB];
    const int tid = threadIdx.x;
    if (tid < NB) sqw[tid] = sqrtf(qw[tid]);
    __syncthreads();
    const int gbase = blockIdx.x * 64;
    const int ibase = blockIdx.y * 64;

#pragma unroll
    for (int p = 0; p < 4; p++) {
        int g_l = (tid >> 4) + 16 * p;
        int i_l = (tid & 15) * 4;
        int g = gbase + g_l;
        float w = sqw[(g / NA) % NB];
        float4 v = (ibase + i_l < DIM)
                 ? *(const float4*)(D + (size_t)g * DIM + ibase + i_l)
                 : make_float4(0.f, 0.f, 0.f, 0.f);
        s[g_l][i_l]     = v.x * w;
        s[g_l][i_l + 1] = v.y * w;
        s[g_l][i_l + 2] = v.z * w;
        s[g_l][i_l + 3] = v.w * w;
    }
    __syncthreads();

    const int i_l = tid >> 2;
    const int gc  = (tid & 3) * 16;
    uint32_t hi[8], lo[8];
#pragma unroll
    for (int q = 0; q < 8; q++) {
        float a = s[gc + 2 * q][i_l];
        float b = s[gc + 2 * q + 1][i_l];
        __nv_bfloat16 ha, la, hb, lb;
        split_bf16(a, ha, la);
        split_bf16(b, hb, lb);
        hi[q] = pack2h(ha, hb);
        lo[q] = pack2h(la, lb);
    }
    size_t ro = (size_t)(ibase + i_l) * GTOT + gbase + gc;
    *(uint4*)(gZh + ro)     = make_uint4(hi[0], hi[1], hi[2], hi[3]);
    *(uint4*)(gZh + ro + 8) = make_uint4(hi[4], hi[5], hi[6], hi[7]);
    *(uint4*)(gZl + ro)     = make_uint4(lo[0], lo[1], lo[2], lo[3]);
    *(uint4*)(gZl + ro + 8) = make_uint4(lo[4], lo[5], lo[6], lo[7]);
}

// ---------------------------------------------------------------- kernel 2
// gram: tile e, split z -> gP[e][z] = A(128 rows Zh) @ B(128 rows Zh|Zl)^T
// 256 threads, 2 CTAs/SM; GBK=64/NSTG=3: 108 phases, 2x longer MMA runs
extern "C" __global__ void __launch_bounds__(256, 2)
gram_mm() {
    extern __shared__ char dsm[];
    const uint32_t sbase = smem_u32(dsm);

    const int e     = blockIdx.x;
    const int split = blockIdx.y;
    const int ibase = cMI[e] * GBM;
    const int jbase = cNJ[e] * GBN;
    const size_t g0 = (size_t)split * KPS;
    const __nv_bfloat16* Brows = cPASS[e] ? gZl : gZh;

    const int tid  = threadIdx.x;
    const int lane = tid & 31, warp = tid >> 5;
    const int wmB  = (warp & 1) * 64;
    const int wnB  = (warp >> 1) * 32;
    const int group = lane >> 2, tig = lane & 3;
    const int frow = lane & 15;
    const int fcol = (lane & 16) ? 8 : 0;

    float acc[4][4][4];
#pragma unroll
    for (int mi = 0; mi < 4; mi++)
#pragma unroll
        for (int nb = 0; nb < 4; nb++)
#pragma unroll
            for (int r = 0; r < 4; r++) acc[mi][nb][r] = 0.f;

    // fill one 64k stage: A 1024 + B 1024 16B chunks, 8 per thread
    auto fill = [&](int it) {
        const uint32_t stg = sbase + (uint32_t)(it % NSTG) * STAGEB;
        const size_t gofs = g0 + (size_t)it * GBK;
#pragma unroll
        for (int p = 0; p < 4; p++) {
            int c = tid + 256 * p;
            int row = c >> 3, col16 = c & 7;
            cp_async16(stg + row * 144 + col16 * 16,
                       gZh + (size_t)(ibase + row) * GTOT + gofs + col16 * 8);
            cp_async16(stg + ASTG + row * 144 + col16 * 16,
                       Brows + (size_t)(jbase + row) * GTOT + gofs + col16 * 8);
        }
        cp_commit();
    };

#pragma unroll
    for (int s = 0; s < NSTG - 1; s++) fill(s);   // prologue: 2 groups

    for (int it = 0; it < TOTIT; ++it) {
        if (it < TOTIT - 1)
            asm volatile("cp.async.wait_group 1;\n" ::: "memory");
        else
            asm volatile("cp.async.wait_group 0;\n" ::: "memory");
        __syncthreads();

        const uint32_t stg = sbase + (uint32_t)(it % NSTG) * STAGEB;
        const uint32_t aU = stg, bU = stg + ASTG;
#pragma unroll
        for (int kk = 0; kk < GBK; kk += 16) {
            uint32_t A4[4][4], B4[2][4];
#pragma unroll
            for (int mi = 0; mi < 4; mi++)
                ldsm4(A4[mi], aU + 2u * ((wmB + 16 * mi + frow) * GPITCH + kk + fcol));
#pragma unroll
            for (int h = 0; h < 2; h++)
                ldsm4(B4[h], bU + 2u * ((wnB + 16 * h + frow) * GPITCH + kk + fcol));
#pragma unroll
            for (int mi = 0; mi < 4; mi++)
#pragma unroll
                for (int nb = 0; nb < 4; nb++)
                    mma_bf16(acc[mi][nb], A4[mi],
                             B4[nb >> 1][nb & 1], B4[nb >> 1][(nb & 1) + 2]);
        }
        const int f = it + (NSTG - 1);
        if (f < TOTIT) fill(f);
    }

    // epilogue: per-tile partial [128][128] fp32
    float* P = gP + ((size_t)(e * SPLITK + split)) * TILE_ELEMS;
#pragma unroll
    for (int mi = 0; mi < 4; mi++) {
        int r1 = wmB + 16 * mi + group;
        int r2 = r1 + 8;
#pragma unroll
        for (int nb = 0; nb < 4; nb++) {
            int c0 = wnB + 8 * nb + 2 * tig;
            P[(size_t)r1 * GBN + c0]     = acc[mi][nb][0];
            P[(size_t)r1 * GBN + c0 + 1] = acc[mi][nb][1];
            P[(size_t)r2 * GBN + c0]     = acc[mi][nb][2];
            P[(size_t)r2 * GBN + c0 + 1] = acc[mi][nb][3];
        }
    }
}

// ---------------------------------------------------------------- kernel 3
extern "C" __global__ void reduce_tc() {
    size_t idx = (size_t)blockIdx.x * 256 + threadIdx.x;
    if (idx >= (size_t)NTILES * TILE_ELEMS) return;
    const int e  = (int)(idx >> 14);
    const int rc = (int)(idx & 16383);
    float sum = 0.f;
#pragma unroll
    for (int p = 0; p < SPLITK; p++)
        sum += gP[(((size_t)(e * SPLITK + p)) << 14) + rc];
    const int r = rc >> 7, c = rc & 127;
    const int i = cMI[e] * GBM + r;
    const int j = cNJ[e] * GBN + c;
    if (i < DIM && j < DIM)
        (cPASS[e] ? gS2 : gS1)[(size_t)i * DIM + j] = sum;
}

// ---------------------------------------------------------------- kernel 4
// M = C1(sym) + C2 + C2^T ; C1 block (bi,bj) computed iff bj >= bi
extern "C" __global__ void sym_kernel() {
    int idx = blockIdx.x * blockDim.x + threadIdx.x;
    if (idx < NDIM2) {
        int i = idx / DIM;
        int j = idx - i * DIM;
        float c1 = ((j >> 7) >= (i >> 7)) ? gS1[idx] : gS1[(size_t)j * DIM + i];
        gM[idx] = c1 + gS2[idx] + gS2[(size_t)j * DIM + i];
    }
}

// ---------------------------------------------------------------- kernel 5
// out = F @ M  (3-term bf16 split; OBM=64 -> 96 CTAs for latency hiding)
extern "C" __global__ void __launch_bounds__(256)
out_kernel(const float* __restrict__ F, float* __restrict__ out) {
    __shared__ __nv_bfloat16 sFh[OBM * FPITCH], sFl[OBM * FPITCH];
    __shared__ __nv_bfloat16 sMh[BK * MPITCH], sMl[BK * MPITCH];

    const int tid   = threadIdx.x;
    const int nbase = blockIdx.x * OBM;
    const int ibase = blockIdx.y * OBN;

    const int lane = tid & 31, warp = tid >> 5;
    const int wm = (warp & 1) * 32;
    const int wn = (warp >> 1) * 32;
    const int group = lane >> 2, tig = lane & 3;
    const int frow = lane & 15;
    const int fcol = (lane & 16) ? 8 : 0;
    const int brow = (lane & 7) + ((lane & 8) ? 8 : 0);
    const int bcol = (lane & 16) ? 8 : 0;

    const uint32_t fhU = smem_u32(sFh), flU = smem_u32(sFl);
    const uint32_t mhU = smem_u32(sMh), mlU = smem_u32(sMl);

    float acc[2][4][4];
#pragma unroll
    for (int mi = 0; mi < 2; mi++)
#pragma unroll
        for (int nb = 0; nb < 4; nb++)
#pragma unroll
            for (int r = 0; r < 4; r++) acc[mi][nb][r] = 0.f;

    const int NIT = (DIM + BK - 1) / BK;

    for (int it = 0; it < NIT; ++it) {
        const int k0 = it * BK;
        {   // F tile: 64 rows x 32 k = 512 float4 chunks, 2 per thread
            const int c = (tid & 7) * 4;
            const bool v = (k0 + c) < DIM;
#pragma unroll
            for (int p = 0; p < 2; p++) {
                int row = (tid >> 3) + 32 * p;
                float4 f = v ? *(const float4*)(F + (size_t)(nbase + row) * DIM + k0 + c)
                             : make_float4(0.f, 0.f, 0.f, 0.f);
                __nv_bfloat16 h[4], l[4];
                split_bf16(f.x, h[0], l[0]);
                split_bf16(f.y, h[1], l[1]);
                split_bf16(f.z, h[2], l[2]);
                split_bf16(f.w, h[3], l[3]);
                int off = row * FPITCH + c;
                *(uint2*)&sFh[off] = make_uint2(pack2h(h[0], h[1]), pack2h(h[2], h[3]));
                *(uint2*)&sFl[off] = make_uint2(pack2h(l[0], l[1]), pack2h(l[2], l[3]));
            }
        }
        {   // M tile: 32 k x 128 i
            const int c = (tid & 31) * 4;
            const bool cv = (ibase + c) < DIM;
#pragma unroll
            for (int p = 0; p < 4; p++) {
                int r = (tid >> 5) + 8 * p;
                int j = k0 + r;
                bool v = cv && (j < DIM);
                float4 m = v ? *(const float4*)(gM + (size_t)j * DIM + ibase + c)
                             : make_float4(0.f, 0.f, 0.f, 0.f);
                __nv_bfloat16 h[4], l[4];
                split_bf16(m.x, h[0], l[0]);
                split_bf16(m.y, h[1], l[1]);
                split_bf16(m.z, h[2], l[2]);
                split_bf16(m.w, h[3], l[3]);
                int off = r * MPITCH + c;
                *(uint2*)&sMh[off] = make_uint2(pack2h(h[0], h[1]), pack2h(h[2], h[3]));
                *(uint2*)&sMl[off] = make_uint2(pack2h(l[0], l[1]), pack2h(l[2], l[3]));
            }
        }
        __syncthreads();

#pragma unroll
        for (int kk = 0; kk < BK; kk += 16) {
            uint32_t Ah[2][4], Al[2][4], Bh[2][4], Bl[2][4];
#pragma unroll
            for (int mi = 0; mi < 2; mi++) {
                uint32_t off = 2u * ((wm + 16 * mi + frow) * FPITCH + kk + fcol);
                ldsm4(Ah[mi], fhU + off);
                ldsm4(Al[mi], flU + off);
            }
#pragma unroll
            for (int h = 0; h < 2; h++) {
                uint32_t off = 2u * ((kk + brow) * MPITCH + wn + 16 * h + bcol);
                ldsm4t(Bh[h], mhU + off);
                ldsm4t(Bl[h], mlU + off);
            }
#pragma unroll
            for (int mi = 0; mi < 2; mi++)
#pragma unroll
                for (int nb = 0; nb < 4; nb++) {
                    const int h = nb >> 1, pr = (nb & 1) * 2;
                    mma_bf16(acc[mi][nb], Ah[mi], Bh[h][pr], Bh[h][pr + 1]);
                    mma_bf16(acc[mi][nb], Ah[mi], Bl[h][pr], Bl[h][pr + 1]);
                    mma_bf16(acc[mi][nb], Al[mi], Bh[h][pr], Bh[h][pr + 1]);
                }
        }
        __syncthreads();
    }

#pragma unroll
    for (int mi = 0; mi < 2; mi++) {
        int n1 = nbase + wm + 16 * mi + group;
        int n2 = n1 + 8;
#pragma unroll
        for (int nb = 0; nb < 4; nb++) {
            int i0 = ibase + wn + 8 * nb + 2 * tig;
            if (i0 < DIM) {
                out[(size_t)n1 * DIM + i0]     = acc[mi][nb][0];
                out[(size_t)n1 * DIM + i0 + 1] = acc[mi][nb][1];
                out[(size_t)n2 * DIM + i0]     = acc[mi][nb][2];
                out[(size_t)n2 * DIM + i0 + 1] = acc[mi][nb][3];
            }
        }
    }
}

// ---------------------------------------------------------------- launch
extern "C" void kernel_launch(void* const* d_in, const int* in_sizes, int n_in,
                              void* d_out, int out_size) {
    const float* F  = (const float*)d_in[0];   // (1024, 680)
    const float* D  = (const float*)d_in[1];   // (48, 24, 48, 680)
    const float* qw = (const float*)d_in[2];   // (24,)
    float* out = (float*)d_out;                // (1024, 680) fp32

    const int gram_smem = NSTG * STAGEB;       // 110592 B
    cudaFuncSetAttribute(gram_mm, cudaFuncAttributeMaxDynamicSharedMemorySize, gram_smem);

    transpose_kernel<<<dim3(GTOT / 64, DIMP / 64), 256>>>(D, qw);

    gram_mm<<<dim3(NTILES, SPLITK), 256, gram_smem>>>();

    reduce_tc<<<(NTILES * TILE_ELEMS + 255) / 256, 256>>>();
    sym_kernel<<<(NDIM2 + 255) / 256, 256>>>();

    dim3 ogrid(BATCH / OBM, (DIM + OBN - 1) / OBN);     // 16 x 6
    out_kernel<<<ogrid, 256>>>(F, out);
}

// round 14
// speedup vs baseline: 1.2037x; 1.0257x over previous
#include <cuda_runtime.h>
#include <cuda_bf16.h>
#include <cstdint>
#include <cstddef>

#define BATCH 1024
#define NA 48
#define NB 24
#define DIM 680
#define DIMP 768                 // padded feature count
#define GTOT (NA*NB*NA)          // 55296
#define NDIM2 (DIM*DIM)

// ---- gram config (unchanged from 433us round) ----
#define SPLITK 8
#define KPS (GTOT/SPLITK)        // 6912
#define GBK 64
#define TOTIT (KPS/GBK)          // 108
#define NSTG 3
#define GBM 128
#define GBN 128
#define GPITCH 72                // bf16 pitch: 64 + 8 pad (144B rows, conflict-free ldsm)
#define ASTG (GBM*GPITCH*2)      // 18432 B
#define STAGEB (2*ASTG)          // 36864 B
#define NTILES 57                // 21 C1 (j>=i) + 36 C2
#define TILE_ELEMS (GBM*GBN)     // 16384

// ---- out_kernel config ----
#define OBM 32                   // F rows per CTA -> 192 CTAs
#define OBN 128                  // i cols per CTA
#define BK 32
#define FPITCH 40
#define MPITCH 136

// ---- scratch (no allocations allowed) ----
__device__ __nv_bfloat16 gZh[(size_t)DIMP * GTOT];   // ~85MB
__device__ __nv_bfloat16 gZl[(size_t)DIMP * GTOT];   // ~85MB
__device__ float gP[(size_t)NTILES * SPLITK * TILE_ELEMS];  // ~29.9MB
__device__ __nv_bfloat16 gFh[(size_t)BATCH * DIM];
__device__ __nv_bfloat16 gFl[(size_t)BATCH * DIM];
__device__ __nv_bfloat16 gMh[NDIM2];
__device__ __nv_bfloat16 gMl[NDIM2];

// tile tables: C1 (pass0, Zh*Zh) on j>=i triangle; C2 (pass1, Zh*Zl) on all 36
__constant__ int cMI[NTILES] = {
    0,0,0,0,0,0, 1,1,1,1,1, 2,2,2,2, 3,3,3, 4,4, 5,
    0,0,0,0,0,0, 1,1,1,1,1,1, 2,2,2,2,2,2, 3,3,3,3,3,3, 4,4,4,4,4,4, 5,5,5,5,5,5};
__constant__ int cNJ[NTILES] = {
    0,1,2,3,4,5, 1,2,3,4,5, 2,3,4,5, 3,4,5, 4,5, 5,
    0,1,2,3,4,5, 0,1,2,3,4,5, 0,1,2,3,4,5, 0,1,2,3,4,5, 0,1,2,3,4,5, 0,1,2,3,4,5};
__constant__ int cPASS[NTILES] = {
    0,0,0,0,0,0,0,0,0,0,0,0,0,0,0,0,0,0,0,0,0,
    1,1,1,1,1,1,1,1,1,1,1,1,1,1,1,1,1,1,
    1,1,1,1,1,1,1,1,1,1,1,1,1,1,1,1,1,1};
// lookup: C1 tile index for block (bi<=bj), C2 tile index for any block
__constant__ int cC1IDX[6][6] = {
    { 0, 1, 2, 3, 4, 5},
    {-1, 6, 7, 8, 9,10},
    {-1,-1,11,12,13,14},
    {-1,-1,-1,15,16,17},
    {-1,-1,-1,-1,18,19},
    {-1,-1,-1,-1,-1,20}};

// ---------------------------------------------------------------- helpers
__device__ __forceinline__ uint32_t smem_u32(const void* p) {
    return (uint32_t)__cvta_generic_to_shared(p);
}
__device__ __forceinline__ void split_bf16(float z, __nv_bfloat16& h, __nv_bfloat16& l) {
    h = __float2bfloat16(z);
    l = __float2bfloat16(z - __bfloat162float(h));
}
__device__ __forceinline__ uint32_t pack2h(__nv_bfloat16 a, __nv_bfloat16 b) {
    uint16_t ua = *reinterpret_cast<uint16_t*>(&a);
    uint16_t ub = *reinterpret_cast<uint16_t*>(&b);
    return (uint32_t)ua | ((uint32_t)ub << 16);
}
__device__ __forceinline__ void cp_async16(uint32_t dst, const void* src) {
    asm volatile("cp.async.cg.shared.global [%0], [%1], 16;\n" :: "r"(dst), "l"(src));
}
__device__ __forceinline__ void cp_commit() {
    asm volatile("cp.async.commit_group;\n" ::: "memory");
}
__device__ __forceinline__ void ldsm4(uint32_t (&r)[4], uint32_t addr) {
    asm volatile("ldmatrix.sync.aligned.m8n8.x4.shared.b16 {%0,%1,%2,%3}, [%4];"
                 : "=r"(r[0]), "=r"(r[1]), "=r"(r[2]), "=r"(r[3]) : "r"(addr));
}
__device__ __forceinline__ void ldsm4t(uint32_t (&r)[4], uint32_t addr) {
    asm volatile("ldmatrix.sync.aligned.m8n8.x4.trans.shared.b16 {%0,%1,%2,%3}, [%4];"
                 : "=r"(r[0]), "=r"(r[1]), "=r"(r[2]), "=r"(r[3]) : "r"(addr));
}
__device__ __forceinline__ void mma_bf16(float (&d)[4], const uint32_t (&a)[4],
                                         uint32_t b0, uint32_t b1) {
    asm volatile(
        "mma.sync.aligned.m16n8k16.row.col.f32.bf16.bf16.f32 "
        "{%0,%1,%2,%3}, {%4,%5,%6,%7}, {%8,%9}, {%0,%1,%2,%3};\n"
        : "+f"(d[0]), "+f"(d[1]), "+f"(d[2]), "+f"(d[3])
        : "r"(a[0]), "r"(a[1]), "r"(a[2]), "r"(a[3]), "r"(b0), "r"(b1));
}

// ---------------------------------------------------------------- kernel 0
// F bf16 split precompute: gFh/gFl[n][k] = split(F[n][k])
extern "C" __global__ void __launch_bounds__(256)
fsplit_kernel(const float* __restrict__ F) {
    size_t idx = ((size_t)blockIdx.x * 256 + threadIdx.x) * 4;
    if (idx >= (size_t)BATCH * DIM) return;
    float4 v = *(const float4*)(F + idx);
    __nv_bfloat16 h[4], l[4];
    split_bf16(v.x, h[0], l[0]);
    split_bf16(v.y, h[1], l[1]);
    split_bf16(v.z, h[2], l[2]);
    split_bf16(v.w, h[3], l[3]);
    *(uint2*)(gFh + idx) = make_uint2(pack2h(h[0], h[1]), pack2h(h[2], h[3]));
    *(uint2*)(gFl + idx) = make_uint2(pack2h(l[0], l[1]), pack2h(l[2], l[3]));
}

// ---------------------------------------------------------------- kernel 1
// transpose + weight + bf16 split: gZh/gZl[i][g] = split( sqrt(qw_g) * D[g][i] )
#define TPP 65
extern "C" __global__ void __launch_bounds__(256)
transpose_kernel(const float* __restrict__ D, const float* __restrict__ qw) {
    __shared__ float s[64][TPP];
    __shared__ float sqw[NB];
    const int tid = threadIdx.x;
    if (tid < NB) sqw[tid] = sqrtf(qw[tid]);
    __syncthreads();
    const int gbase = blockIdx.x * 64;
    const int ibase = blockIdx.y * 64;

#pragma unroll
    for (int p = 0; p < 4; p++) {
        int g_l = (tid >> 4) + 16 * p;
        int i_l = (tid & 15) * 4;
        int g = gbase + g_l;
        float w = sqw[(g / NA) % NB];
        float4 v = (ibase + i_l < DIM)
                 ? *(const float4*)(D + (size_t)g * DIM + ibase + i_l)
                 : make_float4(0.f, 0.f, 0.f, 0.f);
        s[g_l][i_l]     = v.x * w;
        s[g_l][i_l + 1] = v.y * w;
        s[g_l][i_l + 2] = v.z * w;
        s[g_l][i_l + 3] = v.w * w;
    }
    __syncthreads();

    const int i_l = tid >> 2;
    const int gc  = (tid & 3) * 16;
    uint32_t hi[8], lo[8];
#pragma unroll
    for (int q = 0; q < 8; q++) {
        float a = s[gc + 2 * q][i_l];
        float b = s[gc + 2 * q + 1][i_l];
        __nv_bfloat16 ha, la, hb, lb;
        split_bf16(a, ha, la);
        split_bf16(b, hb, lb);
        hi[q] = pack2h(ha, hb);
        lo[q] = pack2h(la, lb);
    }
    size_t ro = (size_t)(ibase + i_l) * GTOT + gbase + gc;
    *(uint4*)(gZh + ro)     = make_uint4(hi[0], hi[1], hi[2], hi[3]);
    *(uint4*)(gZh + ro + 8) = make_uint4(hi[4], hi[5], hi[6], hi[7]);
    *(uint4*)(gZl + ro)     = make_uint4(lo[0], lo[1], lo[2], lo[3]);
    *(uint4*)(gZl + ro + 8) = make_uint4(lo[4], lo[5], lo[6], lo[7]);
}

// ---------------------------------------------------------------- kernel 2
// gram: tile e, split z -> gP[e][z] = A(128 rows Zh) @ B(128 rows Zh|Zl)^T
// 256 threads, 2 CTAs/SM; GBK=64/NSTG=3 (unchanged from 433us round)
extern "C" __global__ void __launch_bounds__(256, 2)
gram_mm() {
    extern __shared__ char dsm[];
    const uint32_t sbase = smem_u32(dsm);

    const int e     = blockIdx.x;
    const int split = blockIdx.y;
    const int ibase = cMI[e] * GBM;
    const int jbase = cNJ[e] * GBN;
    const size_t g0 = (size_t)split * KPS;
    const __nv_bfloat16* Brows = cPASS[e] ? gZl : gZh;

    const int tid  = threadIdx.x;
    const int lane = tid & 31, warp = tid >> 5;
    const int wmB  = (warp & 1) * 64;
    const int wnB  = (warp >> 1) * 32;
    const int group = lane >> 2, tig = lane & 3;
    const int frow = lane & 15;
    const int fcol = (lane & 16) ? 8 : 0;

    float acc[4][4][4];
#pragma unroll
    for (int mi = 0; mi < 4; mi++)
#pragma unroll
        for (int nb = 0; nb < 4; nb++)
#pragma unroll
            for (int r = 0; r < 4; r++) acc[mi][nb][r] = 0.f;

    auto fill = [&](int it) {
        const uint32_t stg = sbase + (uint32_t)(it % NSTG) * STAGEB;
        const size_t gofs = g0 + (size_t)it * GBK;
#pragma unroll
        for (int p = 0; p < 4; p++) {
            int c = tid + 256 * p;
            int row = c >> 3, col16 = c & 7;
            cp_async16(stg + row * 144 + col16 * 16,
                       gZh + (size_t)(ibase + row) * GTOT + gofs + col16 * 8);
            cp_async16(stg + ASTG + row * 144 + col16 * 16,
                       Brows + (size_t)(jbase + row) * GTOT + gofs + col16 * 8);
        }
        cp_commit();
    };

#pragma unroll
    for (int s = 0; s < NSTG - 1; s++) fill(s);   // prologue: 2 groups

    for (int it = 0; it < TOTIT; ++it) {
        if (it < TOTIT - 1)
            asm volatile("cp.async.wait_group 1;\n" ::: "memory");
        else
            asm volatile("cp.async.wait_group 0;\n" ::: "memory");
        __syncthreads();

        const uint32_t stg = sbase + (uint32_t)(it % NSTG) * STAGEB;
        const uint32_t aU = stg, bU = stg + ASTG;
#pragma unroll
        for (int kk = 0; kk < GBK; kk += 16) {
            uint32_t A4[4][4], B4[2][4];
#pragma unroll
            for (int mi = 0; mi < 4; mi++)
                ldsm4(A4[mi], aU + 2u * ((wmB + 16 * mi + frow) * GPITCH + kk + fcol));
#pragma unroll
            for (int h = 0; h < 2; h++)
                ldsm4(B4[h], bU + 2u * ((wnB + 16 * h + frow) * GPITCH + kk + fcol));
#pragma unroll
            for (int mi = 0; mi < 4; mi++)
#pragma unroll
                for (int nb = 0; nb < 4; nb++)
                    mma_bf16(acc[mi][nb], A4[mi],
                             B4[nb >> 1][nb & 1], B4[nb >> 1][(nb & 1) + 2]);
        }
        const int f = it + (NSTG - 1);
        if (f < TOTIT) fill(f);
    }

    float* P = gP + ((size_t)(e * SPLITK + split)) * TILE_ELEMS;
#pragma unroll
    for (int mi = 0; mi < 4; mi++) {
        int r1 = wmB + 16 * mi + group;
        int r2 = r1 + 8;
#pragma unroll
        for (int nb = 0; nb < 4; nb++) {
            int c0 = wnB + 8 * nb + 2 * tig;
            P[(size_t)r1 * GBN + c0]     = acc[mi][nb][0];
            P[(size_t)r1 * GBN + c0 + 1] = acc[mi][nb][1];
            P[(size_t)r2 * GBN + c0]     = acc[mi][nb][2];
            P[(size_t)r2 * GBN + c0 + 1] = acc[mi][nb][3];
        }
    }
}

// ---------------------------------------------------------------- kernel 3
// fused reduce + symmetrize + bf16-split:
//   M[i,j] = C1[min-orient] + C2[i,j] + C2[j,i]  -> gMh/gMl
extern "C" __global__ void __launch_bounds__(256)
finish_kernel() {
    int idx = blockIdx.x * blockDim.x + threadIdx.x;
    if (idx >= NDIM2) return;
    const int i = idx / DIM;
    const int j = idx - i * DIM;
    const int bi = i >> 7, bj = j >> 7;
    const int ri = i & 127, rj = j & 127;

    // C1 (canonical orientation bj>=bi)
    int e1, r1, c1;
    if (bj >= bi) { e1 = cC1IDX[bi][bj]; r1 = ri; c1 = rj; }
    else          { e1 = cC1IDX[bj][bi]; r1 = rj; c1 = ri; }
    float s1 = 0.f;
#pragma unroll
    for (int p = 0; p < SPLITK; p++)
        s1 += gP[(((size_t)(e1 * SPLITK + p)) << 14) + (r1 << 7) + c1];

    // C2 at (i,j)
    const int e2a = 21 + bi * 6 + bj;
    float s2a = 0.f;
#pragma unroll
    for (int p = 0; p < SPLITK; p++)
        s2a += gP[(((size_t)(e2a * SPLITK + p)) << 14) + (ri << 7) + rj];

    // C2 at (j,i)
    const int e2b = 21 + bj * 6 + bi;
    float s2b = 0.f;
#pragma unroll
    for (int p = 0; p < SPLITK; p++)
        s2b += gP[(((size_t)(e2b * SPLITK + p)) << 14) + (rj << 7) + ri];

    float m = s1 + s2a + s2b;
    __nv_bfloat16 h, l;
    split_bf16(m, h, l);
    gMh[idx] = h;
    gMl[idx] = l;
}

// ---------------------------------------------------------------- kernel 4
// out = F @ M  (3-term bf16 split; operands pre-split -> pure copy loads)
// OBM=32 -> 192 CTAs
extern "C" __global__ void __launch_bounds__(256)
out_kernel(float* __restrict__ out) {
    __shared__ __nv_bfloat16 sFh[OBM * FPITCH], sFl[OBM * FPITCH];
    __shared__ __nv_bfloat16 sMh[BK * MPITCH], sMl[BK * MPITCH];

    const int tid   = threadIdx.x;
    const int nbase = blockIdx.x * OBM;
    const int ibase = blockIdx.y * OBN;

    const int lane = tid & 31, warp = tid >> 5;
    const int wn = warp * 16;               // 8 warps x 16 n-cols
    const int group = lane >> 2, tig = lane & 3;
    const int frow = lane & 15;
    const int fcol = (lane & 16) ? 8 : 0;
    const int brow = (lane & 7) + ((lane & 8) ? 8 : 0);
    const int bcol = (lane & 16) ? 8 : 0;

    const uint32_t fhU = smem_u32(sFh), flU = smem_u32(sFl);
    const uint32_t mhU = smem_u32(sMh), mlU = smem_u32(sMl);

    float acc[2][2][4];
#pragma unroll
    for (int mi = 0; mi < 2; mi++)
#pragma unroll
        for (int nb = 0; nb < 2; nb++)
#pragma unroll
            for (int r = 0; r < 4; r++) acc[mi][nb][r] = 0.f;

    const int NIT = (DIM + BK - 1) / BK;    // 22

    for (int it = 0; it < NIT; ++it) {
        const int k0 = it * BK;
        {   // F tile: 32 rows x 32 k, pre-split bf16; 4 elems (8B) per thread per array
            const int row = tid >> 3;
            const int c4  = (tid & 7) * 4;
            const bool v = (k0 + c4 + 4) <= DIM;
            size_t go = (size_t)(nbase + row) * DIM + k0 + c4;
            uint2 h = v ? *(const uint2*)(gFh + go) : make_uint2(0u, 0u);
            uint2 l = v ? *(const uint2*)(gFl + go) : make_uint2(0u, 0u);
            int off = row * FPITCH + c4;
            *(uint2*)&sFh[off] = h;
            *(uint2*)&sFl[off] = l;
        }
        {   // M tile: 32 k-rows x 128 i-cols; 8 elems (16B) per thread x2 passes
            const int c8 = (tid & 15) * 8;
            const bool cv = (ibase + c8 + 8) <= DIM;
#pragma unroll
            for (int p = 0; p < 2; p++) {
                int r = (tid >> 4) + 16 * p;
                int jrow = k0 + r;
                bool v = cv && (jrow < DIM);
                size_t go = (size_t)jrow * DIM + ibase + c8;
                uint4 h = v ? *(const uint4*)(gMh + go) : make_uint4(0u, 0u, 0u, 0u);
                uint4 l = v ? *(const uint4*)(gMl + go) : make_uint4(0u, 0u, 0u, 0u);
                int off = r * MPITCH + c8;
                *(uint4*)&sMh[off] = h;
                *(uint4*)&sMl[off] = l;
            }
        }
        __syncthreads();

#pragma unroll
        for (int kk = 0; kk < BK; kk += 16) {
            uint32_t Ah[2][4], Al[2][4], Bh[4], Bl[4];
#pragma unroll
            for (int mi = 0; mi < 2; mi++) {
                uint32_t off = 2u * ((16 * mi + frow) * FPITCH + kk + fcol);
                ldsm4(Ah[mi], fhU + off);
                ldsm4(Al[mi], flU + off);
            }
            {
                uint32_t off = 2u * ((kk + brow) * MPITCH + wn + bcol);
                ldsm4t(Bh, mhU + off);
                ldsm4t(Bl, mlU + off);
            }
#pragma unroll
            for (int mi = 0; mi < 2; mi++)
#pragma unroll
                for (int nb = 0; nb < 2; nb++) {
                    const int pr = nb * 2;
                    mma_bf16(acc[mi][nb], Ah[mi], Bh[pr], Bh[pr + 1]);
                    mma_bf16(acc[mi][nb], Ah[mi], Bl[pr], Bl[pr + 1]);
                    mma_bf16(acc[mi][nb], Al[mi], Bh[pr], Bh[pr + 1]);
                }
        }
        __syncthreads();
    }

#pragma unroll
    for (int mi = 0; mi < 2; mi++) {
        int n1 = nbase + 16 * mi + group;
        int n2 = n1 + 8;
#pragma unroll
        for (int nb = 0; nb < 2; nb++) {
            int i0 = ibase + wn + 8 * nb + 2 * tig;
            if (i0 < DIM) {
                out[(size_t)n1 * DIM + i0]     = acc[mi][nb][0];
                out[(size_t)n1 * DIM + i0 + 1] = acc[mi][nb][1];
                out[(size_t)n2 * DIM + i0]     = acc[mi][nb][2];
                out[(size_t)n2 * DIM + i0 + 1] = acc[mi][nb][3];
            }
        }
    }
}

// ---------------------------------------------------------------- launch
extern "C" void kernel_launch(void* const* d_in, const int* in_sizes, int n_in,
                              void* d_out, int out_size) {
    const float* F  = (const float*)d_in[0];   // (1024, 680)
    const float* D  = (const float*)d_in[1];   // (48, 24, 48, 680)
    const float* qw = (const float*)d_in[2];   // (24,)
    float* out = (float*)d_out;                // (1024, 680) fp32

    const int gram_smem = NSTG * STAGEB;       // 110592 B
    cudaFuncSetAttribute(gram_mm, cudaFuncAttributeMaxDynamicSharedMemorySize, gram_smem);

    fsplit_kernel<<<(BATCH * DIM / 4 + 255) / 256, 256>>>(F);

    transpose_kernel<<<dim3(GTOT / 64, DIMP / 64), 256>>>(D, qw);

    gram_mm<<<dim3(NTILES, SPLITK), 256, gram_smem>>>();

    finish_kernel<<<(NDIM2 + 255) / 256, 256>>>();

    dim3 ogrid(BATCH / OBM, (DIM + OBN - 1) / OBN);     // 32 x 6
    out_kernel<<<ogrid, 256>>>(out);
}